// round 16
// baseline (speedup 1.0000x reference)
#include <cuda_runtime.h>
#include <cuda_fp16.h>

// Problem constants
#define NW      16384   // words
#define LCH     16      // chars per word
#define CEMB    64      // char emb dim
#define CO      256     // conv out channels
#define DEMB    300     // word emb dim
#define OUTW    556     // 256 + 300
#define WPC     111     // words per CTA (148 * 111 >= 16384)
#define NWARPS  32      // warps per CTA (block = 1024)

// Precomputed conv tables (fp16): M[k][c][o] = sum_e char_emb[c,e]*conv_w[o,e,k]
__device__ __half g_Mh[3 * 128 * 256];

// smem layout offsets (bytes): table rows [c][k][lane16B] = 1536 B/char
#define SM_XPK    196608                   // WPC uint4 (packed chars)
#define SM_XW     (196608 + WPC * 16)      // WPC ints
#define SM_TOTAL  (SM_XW + WPC * 4)        // 198828 B

// ---------------------------------------------------------------------------
// Kernel 1: build tables. grid = 256 (o), block = 128 (c). (unchanged)
// ---------------------------------------------------------------------------
__global__ void build_tables_kernel(const float* __restrict__ ce_w,
                                    const float* __restrict__ conv_w) {
    __shared__ float se[64 * 130];   // padded rows: no STS conflicts
    const int o = blockIdx.x;
    const int c = threadIdx.x;

    for (int i = threadIdx.x; i < 128 * 64; i += 128) {
        int cc = i >> 6;
        int e  = i & 63;
        se[e * 130 + cc] = ce_w[i];
    }
    __syncthreads();

    const float4* wp4 = reinterpret_cast<const float4*>(conv_w + o * (CEMB * 3));
    float a0 = 0.f, a1 = 0.f, a2 = 0.f;
#pragma unroll
    for (int g = 0; g < 16; ++g) {
        float4 f0 = wp4[3 * g + 0];
        float4 f1 = wp4[3 * g + 1];
        float4 f2 = wp4[3 * g + 2];
        float s0 = se[(4 * g + 0) * 130 + c];
        float s1 = se[(4 * g + 1) * 130 + c];
        float s2 = se[(4 * g + 2) * 130 + c];
        float s3 = se[(4 * g + 3) * 130 + c];
        a0 = fmaf(s0, f0.x, a0); a1 = fmaf(s0, f0.y, a1); a2 = fmaf(s0, f0.z, a2);
        a0 = fmaf(s1, f0.w, a0); a1 = fmaf(s1, f1.x, a1); a2 = fmaf(s1, f1.y, a2);
        a0 = fmaf(s2, f1.z, a0); a1 = fmaf(s2, f1.w, a1); a2 = fmaf(s2, f2.x, a2);
        a0 = fmaf(s3, f2.y, a0); a1 = fmaf(s3, f2.z, a1); a2 = fmaf(s3, f2.w, a2);
    }
    g_Mh[(0 * 128 + c) * 256 + o] = __float2half_rn(a0);
    g_Mh[(1 * 128 + c) * 256 + o] = __float2half_rn(a1);
    g_Mh[(2 * 128 + c) * 256 + o] = __float2half_rn(a2);
}

// ---------------------------------------------------------------------------
// Kernel 2: main. grid = 148, block = 1024, ~194.2 KB dyn smem, 1 CTA/SM
// -> 32 warps/SM, reg cap 64. Warp = one word; lane = 8 channels (H8,
// LDS.128 x3 per t). Full 256-channel table per CTA; chars staged once;
// wemb copy un-split. Dual carry chains; cp.async table staging.
// ---------------------------------------------------------------------------
struct H8 { __half2 a, b, c, d; };

__device__ __forceinline__ H8 h8add(H8 x, H8 y) {
    H8 r; r.a = __hadd2(x.a, y.a); r.b = __hadd2(x.b, y.b);
    r.c = __hadd2(x.c, y.c); r.d = __hadd2(x.d, y.d); return r;
}
__device__ __forceinline__ H8 h8max(H8 x, H8 y) {
    H8 r; r.a = __hmax2(x.a, y.a); r.b = __hmax2(x.b, y.b);
    r.c = __hmax2(x.c, y.c); r.d = __hmax2(x.d, y.d); return r;
}

extern "C" __global__ void __launch_bounds__(1024, 1)
wordchar_main_kernel(const int* __restrict__ X,
                     const int* __restrict__ Xword,
                     const float* __restrict__ conv_b,
                     const float* __restrict__ wemb,
                     float* __restrict__ out) {
    extern __shared__ __align__(16) char smem_raw[];
    uint4* xs_pk4 = reinterpret_cast<uint4*>(smem_raw + SM_XPK);
    unsigned* xs_pk = reinterpret_cast<unsigned*>(smem_raw + SM_XPK);
    int* xw_s = reinterpret_cast<int*>(smem_raw + SM_XW);

    const int base = blockIdx.x * WPC;
    const int cnt  = (NW - base < WPC) ? (NW - base) : WPC;

    // ---- staging: full table via cp.async; chars/Xword in its shadow ----
    {
        const char* gbase = reinterpret_cast<const char*>(g_Mh);
        const unsigned sbase = (unsigned)__cvta_generic_to_shared(smem_raw);
        const int ntot4 = 128 * 96;            // 12288 uint4 (16B) chunks
        for (int i = threadIdx.x; i < ntot4; i += blockDim.x) {
            int c  = i / 96;
            int s  = i - c * 96;               // 96 uint4 per 1536B char row
            int k  = s >> 5;                   // 32 uint4 per k-slab
            int ln = s & 31;
            const char* gsrc = gbase + ((size_t)(k * 128 + c) * 512 + ln * 16);
            asm volatile("cp.async.cg.shared.global [%0], [%1], 16;\n"
                         :: "r"(sbase + i * 16), "l"(gsrc));
        }
        asm volatile("cp.async.commit_group;\n" ::: "memory");

        const int4* X4 = reinterpret_cast<const int4*>(X);
        for (int i = threadIdx.x; i < cnt * 4; i += blockDim.x) {
            int4 xi = X4[base * 4 + i];        // coalesced
            xs_pk[i] = (unsigned)xi.x | ((unsigned)xi.y << 8) |
                       ((unsigned)xi.z << 16) | ((unsigned)xi.w << 24);
        }
        for (int i = threadIdx.x; i < cnt; i += blockDim.x)
            xw_s[i] = Xword[base + i];

        asm volatile("cp.async.wait_group 0;\n" ::: "memory");
    }
    __syncthreads();

    const int warp = threadIdx.x >> 5;
    const int lane = threadIdx.x & 31;

    // bias for this lane's 8 channels
    const float4* bp = reinterpret_cast<const float4*>(conv_b + lane * 8);
    const float4 bA = bp[0], bB = bp[1];

    const char* Ms_lane = smem_raw + lane * 16;

    // wemb copy: 75 float4 per word -> lanes cover j, j+32, j+64 (j+64<75)
    const int ja = lane;
    const int jb = lane + 32;
    const int jc = lane + 64;
    const bool pc = (jc < 75);

    const H8 zero = { __float2half2_rn(0.f), __float2half2_rn(0.f),
                      __float2half2_rn(0.f), __float2half2_rn(0.f) };

    for (int wl = warp; wl < cnt; wl += NWARPS) {
        const int w = base + wl;

        // chars: one broadcast LDS.128
        uint4 pkv = xs_pk4[wl];
        unsigned pk[4] = { pkv.x, pkv.y, pkv.z, pkv.w };

        // word-embedding gather kicked off early (the only LDG in the loop)
        const int wi = xw_s[wl];
        const float4* src = reinterpret_cast<const float4*>(wemb + (size_t)wi * DEMB);
        float4* dst = reinterpret_cast<float4*>(out + (size_t)w * OUTW + CO);
        float4 ea, eb, ec;
        ea = src[ja];
        eb = src[jb];
        if (pc) ec = src[jc];

        // ---- chain B warm-up: t=6,7 (m0/m1 only) ----
        H8 c0B, c1B;
        {
            const int c6 = (pk[1] >> 16) & 0xFF;
            const int c7 = (pk[1] >> 24) & 0xFF;
            const char* r6 = Ms_lane + c6 * 1536;
            const char* r7 = Ms_lane + c7 * 1536;
            H8 m0_6 = *reinterpret_cast<const H8*>(r6);
            H8 m0_7 = *reinterpret_cast<const H8*>(r7);
            H8 m1_7 = *reinterpret_cast<const H8*>(r7 + 512);
            c1B = h8add(m1_7, m0_6);   // carry into t=8
            c0B = m0_7;
        }

        // ---- interleaved dual chains: A t=i, B t=i+8 ----
        H8 maxsA, c0A = zero, c1A = zero;
        H8 maxsB;
#pragma unroll
        for (int i = 0; i < 8; ++i) {
            {
                const int cc = (pk[i >> 2] >> ((i & 3) * 8)) & 0xFF;
                const char* rowp = Ms_lane + cc * 1536;
                H8 m0 = *reinterpret_cast<const H8*>(rowp);
                H8 m1 = *reinterpret_cast<const H8*>(rowp + 512);
                H8 m2 = *reinterpret_cast<const H8*>(rowp + 1024);
                H8 y  = h8add(m2, c1A);
                maxsA = (i == 0) ? y : h8max(maxsA, y);
                c1A = h8add(m1, c0A);
                c0A = m0;
            }
            {
                const int t  = i + 8;
                const int cc = (pk[t >> 2] >> ((t & 3) * 8)) & 0xFF;
                const char* rowp = Ms_lane + cc * 1536;
                H8 m0 = *reinterpret_cast<const H8*>(rowp);
                H8 m1 = *reinterpret_cast<const H8*>(rowp + 512);
                H8 m2 = *reinterpret_cast<const H8*>(rowp + 1024);
                H8 y  = h8add(m2, c1B);
                maxsB = (i == 0) ? y : h8max(maxsB, y);
                c1B = h8add(m1, c0B);
                c0B = m0;
            }
        }
        maxsB = h8max(maxsB, c1B);   // t = 16
        maxsB = h8max(maxsB, c0B);   // t = 17
        H8 maxs = h8max(maxsA, maxsB);

        // fp32 bias + relu + store (8 floats = 2x STG.128)
        float2 f0 = __half22float2(maxs.a);
        float2 f1 = __half22float2(maxs.b);
        float2 f2 = __half22float2(maxs.c);
        float2 f3 = __half22float2(maxs.d);
        float4 r0, r1;
        r0.x = fmaxf(f0.x + bA.x, 0.f);
        r0.y = fmaxf(f0.y + bA.y, 0.f);
        r0.z = fmaxf(f1.x + bA.z, 0.f);
        r0.w = fmaxf(f1.y + bA.w, 0.f);
        r1.x = fmaxf(f2.x + bB.x, 0.f);
        r1.y = fmaxf(f2.y + bB.y, 0.f);
        r1.z = fmaxf(f3.x + bB.z, 0.f);
        r1.w = fmaxf(f3.y + bB.w, 0.f);
        float4* op = reinterpret_cast<float4*>(out + (size_t)w * OUTW + lane * 8);
        op[0] = r0;
        op[1] = r1;

        // word-embedding slice stores
        dst[ja] = ea;
        dst[jb] = eb;
        if (pc) dst[jc] = ec;
    }
}

// ---------------------------------------------------------------------------
// Launch
// ---------------------------------------------------------------------------
extern "C" void kernel_launch(void* const* d_in, const int* in_sizes, int n_in,
                              void* d_out, int out_size) {
    const int*   X        = (const int*)  d_in[0];   // [16384,16]
    const int*   X_word   = (const int*)  d_in[1];   // [16384]
    const float* char_emb = (const float*)d_in[2];   // [128,64]
    const float* conv_w   = (const float*)d_in[3];   // [256,64,3]
    const float* conv_b   = (const float*)d_in[4];   // [256]
    const float* word_emb = (const float*)d_in[5];   // [50000,300]
    float*       out      = (float*)d_out;           // [16384,556]

    build_tables_kernel<<<256, 128>>>(char_emb, conv_w);

    cudaFuncSetAttribute(wordchar_main_kernel,
                         cudaFuncAttributeMaxDynamicSharedMemorySize, SM_TOTAL);
    wordchar_main_kernel<<<148, 1024, SM_TOTAL>>>(X, X_word, conv_b, word_emb, out);
}